// round 2
// baseline (speedup 1.0000x reference)
#include <cuda_runtime.h>
#include <math.h>

#define L_DIM 128
#define D_DIM 64
#define M_DIM 256
#define TPB   512
#define TILE  64      // rows per tile; 16 warps x 4 rows

// cen[m][d] transposed: cenT[d][m]
__device__ float g_cenT[D_DIM * M_DIM];

// ---------------------------------------------------------------------------
// Kernel A: cen = conf * (centroid_feats @ W + b), stored transposed [D][M]
// ---------------------------------------------------------------------------
__global__ void cen_kernel(const float* __restrict__ cfeat,
                           const float* __restrict__ conf,
                           const float* __restrict__ W,
                           const float* __restrict__ bias)
{
    int m = blockIdx.x;
    int d = threadIdx.x;
    const float* row = cfeat + m * L_DIM;
    float acc = bias[d];
#pragma unroll 8
    for (int k = 0; k < L_DIM; k++)
        acc = fmaf(row[k], W[k * D_DIM + d], acc);
    g_cenT[d * M_DIM + m] = conf[m] * acc;
}

// ---------------------------------------------------------------------------
// Main kernel. 148 persistent CTAs, 512 threads, 1 CTA/SM.
// Per 64-row tile:
//   Phase A: clu = feats @ W + b   (thread = 4 rows x 2 cols, smem W)
//   Phase N: per-row L2-norm scale
//   Phase B: warp = 4 rows: v = clu . cenT (LDS.128 cen shared by 4 rows),
//            then per-row exact-int distance + warp softmax + fused STG.128
// ---------------------------------------------------------------------------
__global__ __launch_bounds__(TPB, 1)
void main_kernel(const int*   __restrict__ clu_c,
                 const int*   __restrict__ cen_c,
                 const float* __restrict__ feats,
                 const float* __restrict__ bias,
                 const float* __restrict__ Wg,
                 float*       __restrict__ out,
                 int N, int numTiles)
{
    extern __shared__ float sm[];
    float* W_s     = sm;                        // 8192 floats
    float* cenT_s  = W_s + L_DIM * D_DIM;       // 16384
    float* b_s     = cenT_s + D_DIM * M_DIM;    // 64
    float* feats_s = b_s + D_DIM;               // 64*128 = 8192
    float* clu_s   = feats_s + TILE * L_DIM;    // 64*64  = 4096
    float* scale_s = clu_s + TILE * D_DIM;      // 64
    int4*  cm4_s   = (int4*)(scale_s + TILE);   // 256 int4 (x,y,z,|e|^2)
    int*   cb_s    = (int*)(cm4_s + M_DIM);     // 256
    int*   rb_s    = cb_s + M_DIM;              // 64 each
    int*   rx_s    = rb_s + TILE;
    int*   ry_s    = rx_s + TILE;
    int*   rz_s    = ry_s + TILE;
    int*   rn2_s   = rz_s + TILE;

    const int tid  = threadIdx.x;
    const int warp = tid >> 5;
    const int lane = tid & 31;

    // ---- one-time per-CTA staging ----
    for (int i = tid; i < L_DIM * D_DIM; i += TPB) W_s[i] = Wg[i];
    for (int i = tid; i < D_DIM * M_DIM; i += TPB) cenT_s[i] = g_cenT[i];
    if (tid < D_DIM) b_s[tid] = bias[tid];
    for (int m = tid; m < M_DIM; m += TPB) {
        int4 c = ((const int4*)cen_c)[m];
        cb_s[m]  = c.x;
        cm4_s[m] = make_int4(c.y, c.z, c.w, c.y * c.y + c.z * c.z + c.w * c.w);
    }
    __syncthreads();

    for (int tile = blockIdx.x; tile < numTiles; tile += gridDim.x) {
        const int row0 = tile * TILE;
        const int nval = min(TILE, N - row0);

        // ---- load feats tile (float4 coalesced) + row coords ----
        {
            const float4* fg = (const float4*)(feats + (long long)row0 * L_DIM);
            float4* fs = (float4*)feats_s;
            const int nf4 = nval * (L_DIM / 4);
            for (int i = tid; i < nf4; i += TPB) fs[i] = fg[i];
            if (tid < nval) {
                int4 c = ((const int4*)clu_c)[row0 + tid];
                rb_s[tid] = c.x; rx_s[tid] = c.y; ry_s[tid] = c.z; rz_s[tid] = c.w;
                rn2_s[tid] = c.y * c.y + c.z * c.z + c.w * c.w;
            }
        }
        __syncthreads();

        // ---- Phase A: warp q -> rows 4q..4q+3, lane p -> cols 2p,2p+1 ----
        {
            const float* f0 = feats_s + (4 * warp) * L_DIM;
            const float* f1 = f0 + L_DIM;
            const float* f2 = f1 + L_DIM;
            const float* f3 = f2 + L_DIM;
            const float bx = b_s[2 * lane], by = b_s[2 * lane + 1];
            float a0x = bx, a0y = by, a1x = bx, a1y = by;
            float a2x = bx, a2y = by, a3x = bx, a3y = by;
#pragma unroll 2
            for (int k0 = 0; k0 < L_DIM; k0 += 4) {
                const float4 x0 = *(const float4*)(f0 + k0);
                const float4 x1 = *(const float4*)(f1 + k0);
                const float4 x2 = *(const float4*)(f2 + k0);
                const float4 x3 = *(const float4*)(f3 + k0);
#pragma unroll
                for (int kk = 0; kk < 4; kk++) {
                    const float2 w2 = *(const float2*)(W_s + (k0 + kk) * D_DIM + 2 * lane);
                    const float v0 = kk == 0 ? x0.x : kk == 1 ? x0.y : kk == 2 ? x0.z : x0.w;
                    const float v1 = kk == 0 ? x1.x : kk == 1 ? x1.y : kk == 2 ? x1.z : x1.w;
                    const float v2 = kk == 0 ? x2.x : kk == 1 ? x2.y : kk == 2 ? x2.z : x2.w;
                    const float v3 = kk == 0 ? x3.x : kk == 1 ? x3.y : kk == 2 ? x3.z : x3.w;
                    a0x = fmaf(v0, w2.x, a0x); a0y = fmaf(v0, w2.y, a0y);
                    a1x = fmaf(v1, w2.x, a1x); a1y = fmaf(v1, w2.y, a1y);
                    a2x = fmaf(v2, w2.x, a2x); a2y = fmaf(v2, w2.y, a2y);
                    a3x = fmaf(v3, w2.x, a3x); a3y = fmaf(v3, w2.y, a3y);
                }
            }
            float* c0 = clu_s + (4 * warp) * D_DIM + 2 * lane;
            *(float2*)(c0)               = make_float2(a0x, a0y);
            *(float2*)(c0 + D_DIM)       = make_float2(a1x, a1y);
            *(float2*)(c0 + 2 * D_DIM)   = make_float2(a2x, a2y);
            *(float2*)(c0 + 3 * D_DIM)   = make_float2(a3x, a3y);
        }
        __syncthreads();

        // ---- Phase N: per-row normalize scale ----
        if (tid < TILE) {
            const float* cr = clu_s + tid * D_DIM;
            float s = 0.f;
#pragma unroll 8
            for (int d = 0; d < D_DIM; d++) s = fmaf(cr[d], cr[d], s);
            scale_s[tid] = 1.0f / fmaxf(sqrtf(s), 1e-12f);
        }
        __syncthreads();

        // ---- Phase B: warp -> rows 4w..4w+3; lane -> cols lane*8..lane*8+7 ----
        float v0[8], v1[8], v2[8], v3[8];
#pragma unroll
        for (int j = 0; j < 8; j++) { v0[j] = 0.f; v1[j] = 0.f; v2[j] = 0.f; v3[j] = 0.f; }
        {
            const float* cA = clu_s + (4 * warp) * D_DIM;
#pragma unroll 4
            for (int d0 = 0; d0 < D_DIM; d0 += 4) {
                const float4 aA = *(const float4*)(cA + d0);
                const float4 aB = *(const float4*)(cA + D_DIM + d0);
                const float4 aC = *(const float4*)(cA + 2 * D_DIM + d0);
                const float4 aD = *(const float4*)(cA + 3 * D_DIM + d0);
#pragma unroll
                for (int kk = 0; kk < 4; kk++) {
                    const float* ce = cenT_s + (d0 + kk) * M_DIM + lane * 8;
                    const float4 c0 = *(const float4*)(ce);
                    const float4 c1 = *(const float4*)(ce + 4);
                    const float fA = kk == 0 ? aA.x : kk == 1 ? aA.y : kk == 2 ? aA.z : aA.w;
                    const float fB = kk == 0 ? aB.x : kk == 1 ? aB.y : kk == 2 ? aB.z : aB.w;
                    const float fC = kk == 0 ? aC.x : kk == 1 ? aC.y : kk == 2 ? aC.z : aC.w;
                    const float fD = kk == 0 ? aD.x : kk == 1 ? aD.y : kk == 2 ? aD.z : aD.w;
                    const float cc[8] = {c0.x, c0.y, c0.z, c0.w, c1.x, c1.y, c1.z, c1.w};
#pragma unroll
                    for (int j = 0; j < 8; j++) {
                        v0[j] = fmaf(fA, cc[j], v0[j]);
                        v1[j] = fmaf(fB, cc[j], v1[j]);
                        v2[j] = fmaf(fC, cc[j], v2[j]);
                        v3[j] = fmaf(fD, cc[j], v3[j]);
                    }
                }
            }
        }

        // ---- per-row: exact int distance, warp softmax, fused write ----
#pragma unroll
        for (int rr = 0; rr < 4; rr++) {
            const int r = 4 * warp + rr;
            const int row = row0 + r;
            if (row < N) {
                const int rb = rb_s[r], rx = rx_s[r], ry = ry_s[r], rz = rz_s[r];
                const int rn2 = rn2_s[r];
                const float scale = scale_s[r];
                float logit[8];
                float maxl = -3.0e38f;
#pragma unroll
                for (int j = 0; j < 8; j++) {
                    const int m = lane * 8 + j;
                    const int4 cm = cm4_s[m];
                    const int dot = rx * cm.x + ry * cm.y + rz * cm.z;
                    const int d2  = rn2 + cm.w - 2 * dot;   // exact (coords < 1024)
                    const float dist = fmaxf(sqrtf((float)d2), 0.1f);
                    logit[j] = (cb_s[m] == rb) ? -dist : -3.0e38f;
                    maxl = fmaxf(maxl, logit[j]);
                }
#pragma unroll
                for (int off = 16; off; off >>= 1)
                    maxl = fmaxf(maxl, __shfl_xor_sync(0xffffffffu, maxl, off));

                float e[8];
                float sumv = 0.f;
#pragma unroll
                for (int j = 0; j < 8; j++) {
                    e[j] = (logit[j] > -1.0e38f) ? __expf(logit[j] - maxl) : 0.f;
                    sumv += e[j];
                }
#pragma unroll
                for (int off = 16; off; off >>= 1)
                    sumv += __shfl_xor_sync(0xffffffffu, sumv, off);

                const float rinv = (sumv > 0.f) ? (scale / sumv) : 0.f;
                const float* vv = rr == 0 ? v0 : rr == 1 ? v1 : rr == 2 ? v2 : v3;
                float4 o0, o1;
                o0.x = vv[0] * e[0] * rinv; o0.y = vv[1] * e[1] * rinv;
                o0.z = vv[2] * e[2] * rinv; o0.w = vv[3] * e[3] * rinv;
                o1.x = vv[4] * e[4] * rinv; o1.y = vv[5] * e[5] * rinv;
                o1.z = vv[6] * e[6] * rinv; o1.w = vv[7] * e[7] * rinv;
                float4* orow = (float4*)(out + (long long)row * M_DIM + lane * 8);
                orow[0] = o0;
                orow[1] = o1;
            }
        }
        __syncthreads();   // protect smem before next tile's loads
    }
}

// ---------------------------------------------------------------------------
extern "C" void kernel_launch(void* const* d_in, const int* in_sizes, int n_in,
                              void* d_out, int out_size)
{
    const int*   clu_c = (const int*)  d_in[0];
    const int*   cen_c = (const int*)  d_in[1];
    const float* feats = (const float*)d_in[2];
    const float* cfeat = (const float*)d_in[3];
    const float* conf  = (const float*)d_in[4];
    const float* W     = (const float*)d_in[5];
    const float* bias  = (const float*)d_in[6];
    float* out = (float*)d_out;

    const int N = in_sizes[2] / L_DIM;
    const int numTiles = (N + TILE - 1) / TILE;

    // smem bytes: floats (8192+16384+64+8192+4096+64)=36992*4
    //           + ints  (256*4 + 256 + 5*64)=1600*4     -> 154368 B
    const size_t SMEM = (size_t)36992 * 4 + (size_t)1600 * 4;

    cen_kernel<<<M_DIM, D_DIM>>>(cfeat, conf, W, bias);

    cudaFuncSetAttribute(main_kernel,
                         cudaFuncAttributeMaxDynamicSharedMemorySize, (int)SMEM);
    main_kernel<<<148, TPB, SMEM>>>(clu_c, cen_c, feats, bias, W, out, N, numTiles);
}

// round 3
// speedup vs baseline: 1.5983x; 1.5983x over previous
#include <cuda_runtime.h>
#include <math.h>

#define L_DIM 128
#define D_DIM 64
#define M_DIM 256
#define TPB   512
#define TILE  64      // rows per tile; 16 warps x 4 rows

// cen[m][d] transposed: cenT[d][m]
__device__ float g_cenT[D_DIM * M_DIM];

// ---------------------------------------------------------------------------
// Kernel A: cen = conf * (centroid_feats @ W + b), stored transposed [D][M]
// ---------------------------------------------------------------------------
__global__ void cen_kernel(const float* __restrict__ cfeat,
                           const float* __restrict__ conf,
                           const float* __restrict__ W,
                           const float* __restrict__ bias)
{
    int m = blockIdx.x;
    int d = threadIdx.x;
    const float* row = cfeat + m * L_DIM;
    float acc = bias[d];
#pragma unroll 8
    for (int k = 0; k < L_DIM; k++)
        acc = fmaf(row[k], W[k * D_DIM + d], acc);
    g_cenT[d * M_DIM + m] = conf[m] * acc;
}

// ---------------------------------------------------------------------------
// Main kernel. 148 persistent CTAs, 512 threads, 1 CTA/SM.
// Per 64-row tile:
//   Phase A: clu = feats @ W + b   (thread = 4 rows x 2 cols, smem W)
//   Phase N: per-row L2-norm scale
//   Phase B: warp = 4 rows: v = clu . cenT (LDS.128 cen shared by 4 rows),
//            then per-row exact-int distance + warp softmax + fused STG.128
// ---------------------------------------------------------------------------
__global__ __launch_bounds__(TPB, 1)
void main_kernel(const int*   __restrict__ clu_c,
                 const int*   __restrict__ cen_c,
                 const float* __restrict__ feats,
                 const float* __restrict__ bias,
                 const float* __restrict__ Wg,
                 float*       __restrict__ out,
                 int N, int numTiles)
{
    extern __shared__ float sm[];
    float* W_s     = sm;                        // 8192 floats
    float* cenT_s  = W_s + L_DIM * D_DIM;       // 16384
    float* b_s     = cenT_s + D_DIM * M_DIM;    // 64
    float* feats_s = b_s + D_DIM;               // 64*128 = 8192
    float* clu_s   = feats_s + TILE * L_DIM;    // 64*64  = 4096
    float* scale_s = clu_s + TILE * D_DIM;      // 64
    int4*  cm4_s   = (int4*)(scale_s + TILE);   // 256 int4 (x,y,z,|e|^2)
    int*   cb_s    = (int*)(cm4_s + M_DIM);     // 256
    int*   rb_s    = cb_s + M_DIM;              // 64 each
    int*   rx_s    = rb_s + TILE;
    int*   ry_s    = rx_s + TILE;
    int*   rz_s    = ry_s + TILE;
    int*   rn2_s   = rz_s + TILE;

    const int tid  = threadIdx.x;
    const int warp = tid >> 5;
    const int lane = tid & 31;

    // ---- one-time per-CTA staging ----
    for (int i = tid; i < L_DIM * D_DIM; i += TPB) W_s[i] = Wg[i];
    for (int i = tid; i < D_DIM * M_DIM; i += TPB) cenT_s[i] = g_cenT[i];
    if (tid < D_DIM) b_s[tid] = bias[tid];
    for (int m = tid; m < M_DIM; m += TPB) {
        int4 c = ((const int4*)cen_c)[m];
        cb_s[m]  = c.x;
        cm4_s[m] = make_int4(c.y, c.z, c.w, c.y * c.y + c.z * c.z + c.w * c.w);
    }
    __syncthreads();

    for (int tile = blockIdx.x; tile < numTiles; tile += gridDim.x) {
        const int row0 = tile * TILE;
        const int nval = min(TILE, N - row0);

        // ---- load feats tile (float4 coalesced) + row coords ----
        {
            const float4* fg = (const float4*)(feats + (long long)row0 * L_DIM);
            float4* fs = (float4*)feats_s;
            const int nf4 = nval * (L_DIM / 4);
            for (int i = tid; i < nf4; i += TPB) fs[i] = fg[i];
            if (tid < nval) {
                int4 c = ((const int4*)clu_c)[row0 + tid];
                rb_s[tid] = c.x; rx_s[tid] = c.y; ry_s[tid] = c.z; rz_s[tid] = c.w;
                rn2_s[tid] = c.y * c.y + c.z * c.z + c.w * c.w;
            }
        }
        __syncthreads();

        // ---- Phase A: warp q -> rows 4q..4q+3, lane p -> cols 2p,2p+1 ----
        {
            const float* f0 = feats_s + (4 * warp) * L_DIM;
            const float* f1 = f0 + L_DIM;
            const float* f2 = f1 + L_DIM;
            const float* f3 = f2 + L_DIM;
            const float bx = b_s[2 * lane], by = b_s[2 * lane + 1];
            float a0x = bx, a0y = by, a1x = bx, a1y = by;
            float a2x = bx, a2y = by, a3x = bx, a3y = by;
#pragma unroll 2
            for (int k0 = 0; k0 < L_DIM; k0 += 4) {
                const float4 x0 = *(const float4*)(f0 + k0);
                const float4 x1 = *(const float4*)(f1 + k0);
                const float4 x2 = *(const float4*)(f2 + k0);
                const float4 x3 = *(const float4*)(f3 + k0);
#pragma unroll
                for (int kk = 0; kk < 4; kk++) {
                    const float2 w2 = *(const float2*)(W_s + (k0 + kk) * D_DIM + 2 * lane);
                    const float v0 = kk == 0 ? x0.x : kk == 1 ? x0.y : kk == 2 ? x0.z : x0.w;
                    const float v1 = kk == 0 ? x1.x : kk == 1 ? x1.y : kk == 2 ? x1.z : x1.w;
                    const float v2 = kk == 0 ? x2.x : kk == 1 ? x2.y : kk == 2 ? x2.z : x2.w;
                    const float v3 = kk == 0 ? x3.x : kk == 1 ? x3.y : kk == 2 ? x3.z : x3.w;
                    a0x = fmaf(v0, w2.x, a0x); a0y = fmaf(v0, w2.y, a0y);
                    a1x = fmaf(v1, w2.x, a1x); a1y = fmaf(v1, w2.y, a1y);
                    a2x = fmaf(v2, w2.x, a2x); a2y = fmaf(v2, w2.y, a2y);
                    a3x = fmaf(v3, w2.x, a3x); a3y = fmaf(v3, w2.y, a3y);
                }
            }
            float* c0 = clu_s + (4 * warp) * D_DIM + 2 * lane;
            *(float2*)(c0)               = make_float2(a0x, a0y);
            *(float2*)(c0 + D_DIM)       = make_float2(a1x, a1y);
            *(float2*)(c0 + 2 * D_DIM)   = make_float2(a2x, a2y);
            *(float2*)(c0 + 3 * D_DIM)   = make_float2(a3x, a3y);
        }
        __syncthreads();

        // ---- Phase N: per-row normalize scale ----
        if (tid < TILE) {
            const float* cr = clu_s + tid * D_DIM;
            float s = 0.f;
#pragma unroll 8
            for (int d = 0; d < D_DIM; d++) s = fmaf(cr[d], cr[d], s);
            scale_s[tid] = 1.0f / fmaxf(sqrtf(s), 1e-12f);
        }
        __syncthreads();

        // ---- Phase B: warp -> rows 4w..4w+3; lane -> cols lane*8..lane*8+7 ----
        float v0[8], v1[8], v2[8], v3[8];
#pragma unroll
        for (int j = 0; j < 8; j++) { v0[j] = 0.f; v1[j] = 0.f; v2[j] = 0.f; v3[j] = 0.f; }
        {
            const float* cA = clu_s + (4 * warp) * D_DIM;
#pragma unroll 4
            for (int d0 = 0; d0 < D_DIM; d0 += 4) {
                const float4 aA = *(const float4*)(cA + d0);
                const float4 aB = *(const float4*)(cA + D_DIM + d0);
                const float4 aC = *(const float4*)(cA + 2 * D_DIM + d0);
                const float4 aD = *(const float4*)(cA + 3 * D_DIM + d0);
#pragma unroll
                for (int kk = 0; kk < 4; kk++) {
                    const float* ce = cenT_s + (d0 + kk) * M_DIM + lane * 8;
                    const float4 c0 = *(const float4*)(ce);
                    const float4 c1 = *(const float4*)(ce + 4);
                    const float fA = kk == 0 ? aA.x : kk == 1 ? aA.y : kk == 2 ? aA.z : aA.w;
                    const float fB = kk == 0 ? aB.x : kk == 1 ? aB.y : kk == 2 ? aB.z : aB.w;
                    const float fC = kk == 0 ? aC.x : kk == 1 ? aC.y : kk == 2 ? aC.z : aC.w;
                    const float fD = kk == 0 ? aD.x : kk == 1 ? aD.y : kk == 2 ? aD.z : aD.w;
                    const float cc[8] = {c0.x, c0.y, c0.z, c0.w, c1.x, c1.y, c1.z, c1.w};
#pragma unroll
                    for (int j = 0; j < 8; j++) {
                        v0[j] = fmaf(fA, cc[j], v0[j]);
                        v1[j] = fmaf(fB, cc[j], v1[j]);
                        v2[j] = fmaf(fC, cc[j], v2[j]);
                        v3[j] = fmaf(fD, cc[j], v3[j]);
                    }
                }
            }
        }

        // ---- per-row: exact int distance, warp softmax, fused write ----
#pragma unroll
        for (int rr = 0; rr < 4; rr++) {
            const int r = 4 * warp + rr;
            const int row = row0 + r;
            if (row < N) {
                const int rb = rb_s[r], rx = rx_s[r], ry = ry_s[r], rz = rz_s[r];
                const int rn2 = rn2_s[r];
                const float scale = scale_s[r];
                float logit[8];
                float maxl = -3.0e38f;
#pragma unroll
                for (int j = 0; j < 8; j++) {
                    const int m = lane * 8 + j;
                    const int4 cm = cm4_s[m];
                    const int dot = rx * cm.x + ry * cm.y + rz * cm.z;
                    const int d2  = rn2 + cm.w - 2 * dot;   // exact (coords < 1024)
                    const float dist = fmaxf(sqrtf((float)d2), 0.1f);
                    logit[j] = (cb_s[m] == rb) ? -dist : -3.0e38f;
                    maxl = fmaxf(maxl, logit[j]);
                }
#pragma unroll
                for (int off = 16; off; off >>= 1)
                    maxl = fmaxf(maxl, __shfl_xor_sync(0xffffffffu, maxl, off));

                float e[8];
                float sumv = 0.f;
#pragma unroll
                for (int j = 0; j < 8; j++) {
                    e[j] = (logit[j] > -1.0e38f) ? __expf(logit[j] - maxl) : 0.f;
                    sumv += e[j];
                }
#pragma unroll
                for (int off = 16; off; off >>= 1)
                    sumv += __shfl_xor_sync(0xffffffffu, sumv, off);

                const float rinv = (sumv > 0.f) ? (scale / sumv) : 0.f;
                const float* vv = rr == 0 ? v0 : rr == 1 ? v1 : rr == 2 ? v2 : v3;
                float4 o0, o1;
                o0.x = vv[0] * e[0] * rinv; o0.y = vv[1] * e[1] * rinv;
                o0.z = vv[2] * e[2] * rinv; o0.w = vv[3] * e[3] * rinv;
                o1.x = vv[4] * e[4] * rinv; o1.y = vv[5] * e[5] * rinv;
                o1.z = vv[6] * e[6] * rinv; o1.w = vv[7] * e[7] * rinv;
                float4* orow = (float4*)(out + (long long)row * M_DIM + lane * 8);
                orow[0] = o0;
                orow[1] = o1;
            }
        }
        __syncthreads();   // protect smem before next tile's loads
    }
}

// ---------------------------------------------------------------------------
extern "C" void kernel_launch(void* const* d_in, const int* in_sizes, int n_in,
                              void* d_out, int out_size)
{
    const int*   clu_c = (const int*)  d_in[0];
    const int*   cen_c = (const int*)  d_in[1];
    const float* feats = (const float*)d_in[2];
    const float* cfeat = (const float*)d_in[3];
    const float* conf  = (const float*)d_in[4];
    const float* W     = (const float*)d_in[5];
    const float* bias  = (const float*)d_in[6];
    float* out = (float*)d_out;

    const int N = in_sizes[2] / L_DIM;
    const int numTiles = (N + TILE - 1) / TILE;

    // smem bytes: floats (8192+16384+64+8192+4096+64)=36992*4
    //           + ints  (256*4 + 256 + 5*64)=1600*4     -> 154368 B
    const size_t SMEM = (size_t)36992 * 4 + (size_t)1600 * 4;

    cen_kernel<<<M_DIM, D_DIM>>>(cfeat, conf, W, bias);

    cudaFuncSetAttribute(main_kernel,
                         cudaFuncAttributeMaxDynamicSharedMemorySize, (int)SMEM);
    main_kernel<<<148, TPB, SMEM>>>(clu_c, cen_c, feats, bias, W, out, N, numTiles);
}

// round 5
// speedup vs baseline: 2.0563x; 1.2866x over previous
#include <cuda_runtime.h>
#include <math.h>

#define L_DIM 128
#define D_DIM 64
#define M_DIM 256
#define TPB   512
#define TILE  32     // rows per tile; 16 warps x 2 rows

__device__ float g_cenT[D_DIM * M_DIM];   // cen transposed [d][m], ORIGINAL m order
__device__ int   g_order[M_DIM];          // permuted -> original centroid index
__device__ int   g_cs[8], g_ce[8];        // per-batch range in permuted space

// ---------------------------------------------------------------------------
__global__ void cen_kernel(const float* __restrict__ cfeat,
                           const float* __restrict__ conf,
                           const float* __restrict__ W,
                           const float* __restrict__ bias)
{
    int m = blockIdx.x, d = threadIdx.x;
    const float* row = cfeat + m * L_DIM;
    float acc = bias[d];
#pragma unroll 8
    for (int k = 0; k < L_DIM; k++)
        acc = fmaf(row[k], W[k * D_DIM + d], acc);
    g_cenT[d * M_DIM + m] = conf[m] * acc;
}

// counting sort of 256 centroids by batch id (ids are NOT sorted in the data!)
__global__ void prep_order(const int* __restrict__ cen_c)
{
    __shared__ int cnt[8], base[8];
    const int tid = threadIdx.x;
    if (tid < 8) cnt[tid] = 0;
    __syncthreads();
    const int b = cen_c[4 * tid];
    atomicAdd(&cnt[b], 1);
    __syncthreads();
    if (tid == 0) {
        int a = 0;
        for (int bb = 0; bb < 8; bb++) {
            base[bb] = a; g_cs[bb] = a; a += cnt[bb]; g_ce[bb] = a;
        }
    }
    __syncthreads();
    const int pos = atomicAdd(&base[b], 1);
    g_order[pos] = tid;
}

__global__ void zero_kernel(float4* __restrict__ out, long long n4)
{
    long long i = (long long)blockIdx.x * blockDim.x + threadIdx.x;
    const long long stride = (long long)gridDim.x * blockDim.x;
    const float4 z = make_float4(0.f, 0.f, 0.f, 0.f);
    for (; i < n4; i += stride) out[i] = z;
}

// ---------------------------------------------------------------------------
__global__ __launch_bounds__(TPB, 1)
void main_kernel(const int*   __restrict__ clu_c,
                 const int*   __restrict__ cen_c,
                 const float* __restrict__ feats,
                 const float* __restrict__ bias,
                 const float* __restrict__ Wg,
                 float*       __restrict__ out,
                 int N, int numTiles)
{
    extern __shared__ float sm[];
    float* W_s     = sm;                       // 8192
    float* cenT_s  = W_s + L_DIM * D_DIM;      // 16384  (PERMUTED centroid order)
    float* b_s     = cenT_s + D_DIM * M_DIM;   // 64
    float* feats_s = b_s + D_DIM;              // 32*128 = 4096
    float* clu_s   = feats_s + TILE * L_DIM;   // 32*64  = 2048
    float* scale_s = clu_s + TILE * D_DIM;     // 32
    float* vbuf    = scale_s + TILE;           // 16*2*256 = 8192
    int4*  cm4_s   = (int4*)(vbuf + 16 * 2 * M_DIM);  // 256 int4 (PERMUTED)
    int*   ord_s   = (int*)(cm4_s + M_DIM);    // 256
    int*   cs_s    = ord_s + M_DIM;            // 8
    int*   ce_s    = cs_s + 8;                 // 8
    int*   rb_s    = ce_s + 8;                 // 32 each
    int*   rx_s    = rb_s + TILE;
    int*   ry_s    = rx_s + TILE;
    int*   rz_s    = ry_s + TILE;
    int*   rn2_s   = rz_s + TILE;

    const int tid  = threadIdx.x;
    const int warp = tid >> 5;
    const int lane = tid & 31;

    // ---- one-time staging ----
    if (tid < M_DIM) ord_s[tid] = g_order[tid];
    if (tid < 8) { cs_s[tid] = g_cs[tid]; ce_s[tid] = g_ce[tid]; }
    if (tid < D_DIM) b_s[tid] = bias[tid];
    for (int i = tid; i < L_DIM * D_DIM; i += TPB) W_s[i] = Wg[i];
    __syncthreads();   // ord_s ready for gathers below
    for (int i = tid; i < D_DIM * M_DIM; i += TPB) {
        const int d = i >> 8, j = i & 255;
        cenT_s[i] = g_cenT[d * M_DIM + ord_s[j]];
    }
    if (tid < M_DIM) {
        int4 c = ((const int4*)cen_c)[ord_s[tid]];
        cm4_s[tid] = make_int4(c.y, c.z, c.w, c.y*c.y + c.z*c.z + c.w*c.w);
    }
    __syncthreads();

    for (int tile = blockIdx.x; tile < numTiles; tile += gridDim.x) {
        const int row0 = tile * TILE;
        const int nval = min(TILE, N - row0);

        // ---- load feats tile + row coords ----
        {
            const float4* fg = (const float4*)(feats + (long long)row0 * L_DIM);
            float4* fs = (float4*)feats_s;
            for (int i = tid; i < nval * (L_DIM/4); i += TPB) fs[i] = fg[i];
            if (tid < nval) {
                int4 c = ((const int4*)clu_c)[row0 + tid];
                rb_s[tid] = c.x; rx_s[tid] = c.y; ry_s[tid] = c.z; rz_s[tid] = c.w;
                rn2_s[tid] = c.y*c.y + c.z*c.z + c.w*c.w;
            }
        }
        __syncthreads();

        // ---- Phase A: warp w -> rows 2w,2w+1; lane -> cols 2lane,2lane+1 ----
        {
            const float* f0 = feats_s + (2*warp) * L_DIM;
            const float* f1 = f0 + L_DIM;
            float a00 = b_s[2*lane], a01 = b_s[2*lane+1];
            float a10 = a00, a11 = a01;
#pragma unroll 4
            for (int k = 0; k < L_DIM; k++) {
                float x0 = f0[k], x1 = f1[k];
                float2 w2 = *(const float2*)(W_s + k * D_DIM + 2*lane);
                a00 = fmaf(x0, w2.x, a00); a01 = fmaf(x0, w2.y, a01);
                a10 = fmaf(x1, w2.x, a10); a11 = fmaf(x1, w2.y, a11);
            }
            *(float2*)(clu_s + (2*warp)*D_DIM + 2*lane)   = make_float2(a00, a01);
            *(float2*)(clu_s + (2*warp+1)*D_DIM + 2*lane) = make_float2(a10, a11);
        }
        __syncthreads();

        // ---- Phase N: per-row L2-norm scale ----
        if (tid < TILE) {
            const float* cr = clu_s + tid * D_DIM;
            float s = 0.f;
#pragma unroll 8
            for (int d = 0; d < D_DIM; d++) s = fmaf(cr[d], cr[d], s);
            scale_s[tid] = 1.0f / fmaxf(sqrtf(s), 1e-12f);
        }
        __syncthreads();

        // ---- Phase B: only this row's batch range (contiguous in permuted space) ----
        for (int rr = 0; rr < 2; rr++) {
            const int r = 2*warp + rr;
            const int row = row0 + r;
            if (row >= N) continue;
            const int rb = rb_s[r];
            const int s = cs_s[rb], e = ce_s[rb];
            const int len = e - s;
            if (len <= 0) continue;                 // row stays zero
            const int nc = (len + 31) >> 5;
            const int rx = rx_s[r], ry = ry_s[r], rz = rz_s[r], rn2 = rn2_s[r];
            float* vb = vbuf + (warp*2 + rr) * M_DIM;
            const float* cr = clu_s + r * D_DIM;

            // pass 1: dot products + running max of logits
            float maxl = -3.0e38f;
            for (int c = 0; c < nc; c++) {
                const int jj = s + (c << 5) + lane;       // permuted index
                const bool val = jj < e;
                const int j = val ? jj : s;
                float v0 = 0.f, v1 = 0.f, v2 = 0.f, v3 = 0.f;
#pragma unroll 8
                for (int d = 0; d < D_DIM; d += 4) {
                    v0 = fmaf(cr[d],   cenT_s[ d   *M_DIM + j], v0);
                    v1 = fmaf(cr[d+1], cenT_s[(d+1)*M_DIM + j], v1);
                    v2 = fmaf(cr[d+2], cenT_s[(d+2)*M_DIM + j], v2);
                    v3 = fmaf(cr[d+3], cenT_s[(d+3)*M_DIM + j], v3);
                }
                vb[(c << 5) + lane] = (v0 + v1) + (v2 + v3);
                const int4 cm = cm4_s[j];
                const int dot = rx*cm.x + ry*cm.y + rz*cm.z;
                const float dist = fmaxf(sqrtf((float)(rn2 + cm.w - 2*dot)), 0.1f);
                if (val) maxl = fmaxf(maxl, -dist);
            }
#pragma unroll
            for (int off = 16; off; off >>= 1)
                maxl = fmaxf(maxl, __shfl_xor_sync(0xffffffffu, maxl, off));

            // pass 2: exp, accumulate sum, fold into vb
            float sumv = 0.f;
            for (int c = 0; c < nc; c++) {
                const int jj = s + (c << 5) + lane;
                const bool val = jj < e;
                const int j = val ? jj : s;
                const int4 cm = cm4_s[j];
                const int dot = rx*cm.x + ry*cm.y + rz*cm.z;
                const float dist = fmaxf(sqrtf((float)(rn2 + cm.w - 2*dot)), 0.1f);
                const float ee = val ? __expf(-dist - maxl) : 0.f;
                vb[(c << 5) + lane] *= ee;
                sumv += ee;
            }
#pragma unroll
            for (int off = 16; off; off >>= 1)
                sumv += __shfl_xor_sync(0xffffffffu, sumv, off);

            // pass 3: scatter valid columns back to ORIGINAL indices
            const float rinv = scale_s[r] / sumv;
            float* orow = out + (long long)row * M_DIM;
            for (int c = 0; c < nc; c++) {
                const int jj = s + (c << 5) + lane;
                if (jj < e)
                    orow[ord_s[jj]] = vb[(c << 5) + lane] * rinv;
            }
        }
        __syncthreads();
    }
}

// ---------------------------------------------------------------------------
extern "C" void kernel_launch(void* const* d_in, const int* in_sizes, int n_in,
                              void* d_out, int out_size)
{
    const int*   clu_c = (const int*)  d_in[0];
    const int*   cen_c = (const int*)  d_in[1];
    const float* feats = (const float*)d_in[2];
    const float* cfeat = (const float*)d_in[3];
    const float* conf  = (const float*)d_in[4];
    const float* W     = (const float*)d_in[5];
    const float* bias  = (const float*)d_in[6];
    float* out = (float*)d_out;

    const int N = in_sizes[2] / L_DIM;
    const int numTiles = (N + TILE - 1) / TILE;

    // smem: 39008 floats + 1456 ints = 161856 B
    const size_t SMEM = (size_t)39008 * 4 + (size_t)1456 * 4;

    zero_kernel<<<2048, 256>>>((float4*)out, (long long)out_size / 4);
    prep_order<<<1, M_DIM>>>(cen_c);
    cen_kernel<<<M_DIM, D_DIM>>>(cfeat, conf, W, bias);

    cudaFuncSetAttribute(main_kernel,
                         cudaFuncAttributeMaxDynamicSharedMemorySize, (int)SMEM);
    main_kernel<<<148, TPB, SMEM>>>(clu_c, cen_c, feats, bias, W, out, N, numTiles);
}

// round 6
// speedup vs baseline: 2.4834x; 1.2077x over previous
#include <cuda_runtime.h>
#include <math.h>

#define L_DIM 128
#define D_DIM 64
#define M_DIM 256
#define TPB   512
#define TILE  64     // 16 warps x 4 rows

__device__ float g_cenT[D_DIM * M_DIM];   // cen transposed [d][m], original order
__device__ int   g_order[M_DIM];
__device__ int   g_cs[8], g_ce[8];

__global__ void cen_kernel(const float* __restrict__ cfeat,
                           const float* __restrict__ conf,
                           const float* __restrict__ W,
                           const float* __restrict__ bias)
{
    int m = blockIdx.x, d = threadIdx.x;
    const float* row = cfeat + m * L_DIM;
    float acc = bias[d];
#pragma unroll 8
    for (int k = 0; k < L_DIM; k++)
        acc = fmaf(row[k], W[k * D_DIM + d], acc);
    g_cenT[d * M_DIM + m] = conf[m] * acc;
}

// counting sort of centroids by batch id (ids are NOT sorted in the data)
__global__ void prep_order(const int* __restrict__ cen_c)
{
    __shared__ int cnt[8], base[8];
    const int tid = threadIdx.x;
    if (tid < 8) cnt[tid] = 0;
    __syncthreads();
    const int b = cen_c[4 * tid];
    atomicAdd(&cnt[b], 1);
    __syncthreads();
    if (tid == 0) {
        int a = 0;
        for (int bb = 0; bb < 8; bb++) {
            base[bb] = a; g_cs[bb] = a; a += cnt[bb]; g_ce[bb] = a;
        }
    }
    __syncthreads();
    const int pos = atomicAdd(&base[b], 1);
    g_order[pos] = tid;
}

__global__ void zero_kernel(float4* __restrict__ out, long long n4)
{
    long long i = (long long)blockIdx.x * blockDim.x + threadIdx.x;
    const long long stride = (long long)gridDim.x * blockDim.x;
    const float4 z = make_float4(0.f, 0.f, 0.f, 0.f);
    for (; i < n4; i += stride) out[i] = z;
}

__global__ __launch_bounds__(TPB, 1)
void main_kernel(const int*   __restrict__ clu_c,
                 const int*   __restrict__ cen_c,
                 const float* __restrict__ feats,
                 const float* __restrict__ bias,
                 const float* __restrict__ Wg,
                 float*       __restrict__ out,
                 int N, int numTiles)
{
    extern __shared__ float sm[];
    float* W_s     = sm;                       // 8192
    float* cenT_s  = W_s + L_DIM * D_DIM;      // 16384 (permuted order)
    float* b_s     = cenT_s + D_DIM * M_DIM;   // 64
    float* feats_s = b_s + D_DIM;              // 64*128 = 8192
    float* clu_s   = feats_s + TILE * L_DIM;   // 64*64  = 4096
    int4*  cm4_s   = (int4*)(clu_s + TILE * D_DIM);  // 256 int4 (permuted)
    int*   ord_s   = (int*)(cm4_s + M_DIM);    // 256
    int*   cs_s    = ord_s + M_DIM;            // 8
    int*   ce_s    = cs_s + 8;                 // 8
    int*   rb_s    = ce_s + 8;                 // 64 each
    int*   rx_s    = rb_s + TILE;
    int*   ry_s    = rx_s + TILE;
    int*   rz_s    = ry_s + TILE;
    int*   rn2_s   = rz_s + TILE;

    const int tid  = threadIdx.x;
    const int warp = tid >> 5;
    const int lane = tid & 31;

    // ---- one-time staging ----
    if (tid < M_DIM) ord_s[tid] = g_order[tid];
    if (tid < 8) { cs_s[tid] = g_cs[tid]; ce_s[tid] = g_ce[tid]; }
    if (tid < D_DIM) b_s[tid] = bias[tid];
    for (int i = tid; i < L_DIM * D_DIM; i += TPB) W_s[i] = Wg[i];
    __syncthreads();   // ord_s ready
    for (int i = tid; i < D_DIM * M_DIM; i += TPB) {
        const int d = i >> 8, j = i & 255;
        cenT_s[i] = g_cenT[d * M_DIM + ord_s[j]];
    }
    if (tid < M_DIM) {
        int4 c = ((const int4*)cen_c)[ord_s[tid]];
        cm4_s[tid] = make_int4(c.y, c.z, c.w, c.y*c.y + c.z*c.z + c.w*c.w);
    }
    __syncthreads();

    for (int tile = blockIdx.x; tile < numTiles; tile += gridDim.x) {
        const int row0 = tile * TILE;
        const int nval = min(TILE, N - row0);

        // ---- load feats tile (zero-pad invalid rows) + row coords ----
        {
            const float4* fg = (const float4*)(feats + (long long)row0 * L_DIM);
            float4* fs = (float4*)feats_s;
            for (int i = tid; i < TILE * (L_DIM/4); i += TPB) {
                const int row = i >> 5;      // 32 float4 per row
                fs[i] = (row < nval) ? fg[i] : make_float4(0.f, 0.f, 0.f, 0.f);
            }
            if (tid < TILE) {
                if (tid < nval) {
                    int4 c = ((const int4*)clu_c)[row0 + tid];
                    rb_s[tid] = c.x; rx_s[tid] = c.y; ry_s[tid] = c.z; rz_s[tid] = c.w;
                    rn2_s[tid] = c.y*c.y + c.z*c.z + c.w*c.w;
                } else rb_s[tid] = -1;
            }
        }
        __syncthreads();

        // ---- Phase A: warp -> rows 4w..4w+3; lane -> cols 2lane,2lane+1 ----
        float sc0, sc1, sc2, sc3;
        {
            const float* f0 = feats_s + (4*warp) * L_DIM;
            const float* f1 = f0 + L_DIM;
            const float* f2 = f1 + L_DIM;
            const float* f3 = f2 + L_DIM;
            const float bx = b_s[2*lane], by = b_s[2*lane+1];
            float a0x=bx,a0y=by,a1x=bx,a1y=by,a2x=bx,a2y=by,a3x=bx,a3y=by;
#pragma unroll 2
            for (int k0 = 0; k0 < L_DIM; k0 += 4) {
                const float4 x0 = *(const float4*)(f0 + k0);
                const float4 x1 = *(const float4*)(f1 + k0);
                const float4 x2 = *(const float4*)(f2 + k0);
                const float4 x3 = *(const float4*)(f3 + k0);
                const float* p0 = (const float*)&x0;
                const float* p1 = (const float*)&x1;
                const float* p2 = (const float*)&x2;
                const float* p3 = (const float*)&x3;
#pragma unroll
                for (int kk = 0; kk < 4; kk++) {
                    const float2 w2 = *(const float2*)(W_s + (k0+kk)*D_DIM + 2*lane);
                    a0x = fmaf(p0[kk], w2.x, a0x); a0y = fmaf(p0[kk], w2.y, a0y);
                    a1x = fmaf(p1[kk], w2.x, a1x); a1y = fmaf(p1[kk], w2.y, a1y);
                    a2x = fmaf(p2[kk], w2.x, a2x); a2y = fmaf(p2[kk], w2.y, a2y);
                    a3x = fmaf(p3[kk], w2.x, a3x); a3y = fmaf(p3[kk], w2.y, a3y);
                }
            }
            float* c0 = clu_s + (4*warp)*D_DIM + 2*lane;
            *(float2*)(c0)             = make_float2(a0x, a0y);
            *(float2*)(c0 +   D_DIM)   = make_float2(a1x, a1y);
            *(float2*)(c0 + 2*D_DIM)   = make_float2(a2x, a2y);
            *(float2*)(c0 + 3*D_DIM)   = make_float2(a3x, a3y);

            // in-warp L2 norms (scale kept in registers, all lanes)
            float q0 = a0x*a0x + a0y*a0y;
            float q1 = a1x*a1x + a1y*a1y;
            float q2 = a2x*a2x + a2y*a2y;
            float q3 = a3x*a3x + a3y*a3y;
#pragma unroll
            for (int off = 16; off; off >>= 1) {
                q0 += __shfl_xor_sync(0xffffffffu, q0, off);
                q1 += __shfl_xor_sync(0xffffffffu, q1, off);
                q2 += __shfl_xor_sync(0xffffffffu, q2, off);
                q3 += __shfl_xor_sync(0xffffffffu, q3, off);
            }
            sc0 = 1.0f / fmaxf(sqrtf(q0), 1e-12f);
            sc1 = 1.0f / fmaxf(sqrtf(q1), 1e-12f);
            sc2 = 1.0f / fmaxf(sqrtf(q2), 1e-12f);
            sc3 = 1.0f / fmaxf(sqrtf(q3), 1e-12f);
        }
        __syncwarp();   // clu_s warp-private: warp-level RAW only

        // ---- Phase B: per row, only its batch range (contiguous permuted) ----
#pragma unroll
        for (int rr = 0; rr < 4; rr++) {
            const int r = 4*warp + rr;
            const int row = row0 + r;
            if (row >= N) continue;
            const int rb = rb_s[r];
            const int s = cs_s[rb], e = ce_s[rb];
            if (e <= s) continue;
            const int nc = (e - s + 31) >> 5;
            const int rx = rx_s[r], ry = ry_s[r], rz = rz_s[r], rn2 = rn2_s[r];
            const float* cr = clu_s + r * D_DIM;
            const float scale = rr == 0 ? sc0 : rr == 1 ? sc1 : rr == 2 ? sc2 : sc3;

            float v[8], dd[8];
            float maxl = -3.0e38f;
#pragma unroll
            for (int c = 0; c < 8; c++) {
                if (c >= nc) break;
                const int jj = s + (c << 5) + lane;
                const bool val = jj < e;
                const int j = val ? jj : s;
                float v0 = 0.f, v1 = 0.f, v2 = 0.f, v3 = 0.f;
#pragma unroll 4
                for (int d = 0; d < D_DIM; d += 4) {
                    const float4 a = *(const float4*)(cr + d);
                    v0 = fmaf(a.x, cenT_s[ d   *M_DIM + j], v0);
                    v1 = fmaf(a.y, cenT_s[(d+1)*M_DIM + j], v1);
                    v2 = fmaf(a.z, cenT_s[(d+2)*M_DIM + j], v2);
                    v3 = fmaf(a.w, cenT_s[(d+3)*M_DIM + j], v3);
                }
                v[c] = (v0 + v1) + (v2 + v3);
                const int4 cm = cm4_s[j];
                const int dot = rx*cm.x + ry*cm.y + rz*cm.z;
                dd[c] = fmaxf(sqrtf((float)(rn2 + cm.w - 2*dot)), 0.1f);
                if (val) maxl = fmaxf(maxl, -dd[c]);
            }
#pragma unroll
            for (int off = 16; off; off >>= 1)
                maxl = fmaxf(maxl, __shfl_xor_sync(0xffffffffu, maxl, off));

            float sumv = 0.f;
#pragma unroll
            for (int c = 0; c < 8; c++) {
                if (c >= nc) break;
                const int jj = s + (c << 5) + lane;
                const float ee = (jj < e) ? __expf(-dd[c] - maxl) : 0.f;
                dd[c] = ee;
                sumv += ee;
            }
#pragma unroll
            for (int off = 16; off; off >>= 1)
                sumv += __shfl_xor_sync(0xffffffffu, sumv, off);

            const float rinv = scale / sumv;
            float* orow = out + (long long)row * M_DIM;
#pragma unroll
            for (int c = 0; c < 8; c++) {
                if (c >= nc) break;
                const int jj = s + (c << 5) + lane;
                if (jj < e) orow[ord_s[jj]] = v[c] * dd[c] * rinv;
            }
        }
        __syncthreads();   // all phase-A feats reads done before next load
    }
}

extern "C" void kernel_launch(void* const* d_in, const int* in_sizes, int n_in,
                              void* d_out, int out_size)
{
    const int*   clu_c = (const int*)  d_in[0];
    const int*   cen_c = (const int*)  d_in[1];
    const float* feats = (const float*)d_in[2];
    const float* cfeat = (const float*)d_in[3];
    const float* conf  = (const float*)d_in[4];
    const float* W     = (const float*)d_in[5];
    const float* bias  = (const float*)d_in[6];
    float* out = (float*)d_out;

    const int N = in_sizes[2] / L_DIM;
    const int numTiles = (N + TILE - 1) / TILE;

    // smem: floats 36928 + ints 1616 -> 154176 B
    const size_t SMEM = (size_t)36928 * 4 + (size_t)1616 * 4;

    zero_kernel<<<2048, 256>>>((float4*)out, (long long)out_size / 4);
    prep_order<<<1, M_DIM>>>(cen_c);
    cen_kernel<<<M_DIM, D_DIM>>>(cfeat, conf, W, bias);

    cudaFuncSetAttribute(main_kernel,
                         cudaFuncAttributeMaxDynamicSharedMemorySize, (int)SMEM);
    main_kernel<<<148, TPB, SMEM>>>(clu_c, cen_c, feats, bias, W, out, N, numTiles);
}